// round 14
// baseline (speedup 1.0000x reference)
#include <cuda_runtime.h>
#include <math.h>

#define B_   32
#define NF_  128
#define FLAT_ 784
#define HID2_ 392
#define EO_  64
#define FIN_ 8192
#define FHID_ 4096
#define OUT_ 53

// ---------------- scratch (static device allocations) ----------------
// activation pair-planes: uint2 = (hi bf16x2, lo bf16x2) over adjacent ci
__device__ uint2 g_p1[32 * 16 * 112 * 112];
__device__ uint2 g_p2[32 * 32 * 56 * 56];
__device__ float g_f [32 * 128 * 28 * 28];
__device__ float g_lg[32 * 128];
__device__ float g_at[32 * 128];
__device__ float g_h1[32 * 128 * 784];
__device__ float g_h2[32 * 128 * 392];
__device__ float g_e [32 * 8192];
__device__ float g_g1[32 * 8192];
__device__ float g_g2[32 * 4096];
// conv weights interleaved: [tap][cip][co][2] (hi, lo)
__device__ unsigned g_w2i[9 * 16 * 64 * 2];
__device__ unsigned g_w3i[9 * 32 * 128 * 2];

// ---------------- bf16 split helpers ----------------
__device__ __forceinline__ void split2(float x, float y, unsigned& h, unsigned& l) {
    asm("cvt.rn.bf16x2.f32 %0, %1, %2;" : "=r"(h) : "f"(y), "f"(x));
    float rx = x - __uint_as_float(h << 16);
    float ry = y - __uint_as_float(h & 0xffff0000u);
    asm("cvt.rn.bf16x2.f32 %0, %1, %2;" : "=r"(l) : "f"(ry), "f"(rx));
}
__device__ __forceinline__ void mma_bf16(float* c, const unsigned* a, const unsigned* b) {
    asm("mma.sync.aligned.m16n8k16.row.col.f32.bf16.bf16.f32 "
        "{%0,%1,%2,%3}, {%4,%5,%6,%7}, {%8,%9}, {%0,%1,%2,%3};"
        : "+f"(c[0]), "+f"(c[1]), "+f"(c[2]), "+f"(c[3])
        : "r"(a[0]), "r"(a[1]), "r"(a[2]), "r"(a[3]), "r"(b[0]), "r"(b[1]));
}

// ---------------- cp.async helpers ----------------
__device__ __forceinline__ void cpa16(unsigned dst, const void* src, bool pred) {
    int b = pred ? 16 : 0;
    asm volatile("cp.async.cg.shared.global [%0], [%1], 16, %2;" :: "r"(dst), "l"(src), "r"(b));
}
__device__ __forceinline__ void cpa4(unsigned dst, const void* src, bool pred) {
    int b = pred ? 4 : 0;
    asm volatile("cp.async.ca.shared.global [%0], [%1], 4, %2;" :: "r"(dst), "l"(src), "r"(b));
}
__device__ __forceinline__ void cpa_commit() {
    asm volatile("cp.async.commit_group;" ::: "memory");
}
__device__ __forceinline__ void cpa_wait0() {
    asm volatile("cp.async.wait_group 0;" ::: "memory");
}
__device__ __forceinline__ void cpa_wait1() {
    asm volatile("cp.async.wait_group 1;" ::: "memory");
}

// ---------------- conv1: fp32 conv3x3+bias+relu+pool -> interleaved pair planes ----------------
__global__ __launch_bounds__(256)
void conv1_kernel(const float* __restrict__ in, const float* __restrict__ w,
                  const float* __restrict__ bias, uint2* __restrict__ outP)
{
    const int CI = 3, CO_T = 8, H = 224, W = 224;
    __shared__ float sw[CO_T * CI * 9];
    const int tid = threadIdx.x;
    const int co0 = blockIdx.y * CO_T;
    const int b   = blockIdx.z;

    for (int i = tid; i < CO_T * CI * 9; i += 256)
        sw[i] = w[(long)co0 * CI * 9 + i];
    __syncthreads();

    const int HP = 112, WP = 112;
    const int p = blockIdx.x * 256 + tid;
    const int py = p / WP, px = p % WP;
    const int y0 = 2 * py, x0 = 2 * px;

    float acc[CO_T][4];
#pragma unroll
    for (int t = 0; t < CO_T; t++)
        acc[t][0] = acc[t][1] = acc[t][2] = acc[t][3] = 0.f;

    for (int ci = 0; ci < CI; ci++) {
        const float* ip = in + ((long)(b * CI + ci)) * H * W;
        float v[4][4];
#pragma unroll
        for (int r = 0; r < 4; r++) {
            const int yy = y0 - 1 + r;
            const bool yok = (yy >= 0) && (yy < H);
#pragma unroll
            for (int c = 0; c < 4; c++) {
                const int xx = x0 - 1 + c;
                const bool ok = yok && (xx >= 0) && (xx < W);
                v[r][c] = ok ? __ldg(ip + (long)yy * W + xx) : 0.f;
            }
        }
        const float* swc = sw + ci * 9;
#pragma unroll
        for (int t = 0; t < CO_T; t++) {
            const float* wt = swc + t * CI * 9;
#pragma unroll
            for (int ky = 0; ky < 3; ky++)
#pragma unroll
                for (int kx = 0; kx < 3; kx++) {
                    const float wv = wt[ky * 3 + kx];
                    acc[t][0] = fmaf(v[ky    ][kx    ], wv, acc[t][0]);
                    acc[t][1] = fmaf(v[ky    ][kx + 1], wv, acc[t][1]);
                    acc[t][2] = fmaf(v[ky + 1][kx    ], wv, acc[t][2]);
                    acc[t][3] = fmaf(v[ky + 1][kx + 1], wv, acc[t][3]);
                }
        }
    }
    const int cop0 = co0 >> 1;
#pragma unroll
    for (int t = 0; t < 4; t++) {
        float v0 = fmaxf(fmaxf(acc[2*t][0], acc[2*t][1]), fmaxf(acc[2*t][2], acc[2*t][3])) + bias[co0 + 2*t];
        float v1 = fmaxf(fmaxf(acc[2*t+1][0], acc[2*t+1][1]), fmaxf(acc[2*t+1][2], acc[2*t+1][3])) + bias[co0 + 2*t + 1];
        v0 = fmaxf(v0, 0.f); v1 = fmaxf(v1, 0.f);
        unsigned h, l;
        split2(v0, v1, h, l);
        outP[((long)(b * 16 + cop0 + t) * HP + py) * WP + px] = make_uint2(h, l);
    }
}

// ---------------- conv weight prep: -> [tap][cip][co][2] interleaved ----------------
__global__ void conv_wprep_kernel(const float* __restrict__ w,
                                  unsigned* __restrict__ wio, int CI, int CO)
{
    const int idx = blockIdx.x * blockDim.x + threadIdx.x;
    const int CIP = CI >> 1;
    const int total = 9 * CIP * CO;
    if (idx >= total) return;
    const int co  = idx % CO;
    const int rest = idx / CO;
    const int cip = rest % CIP;
    const int tap = rest / CIP;
    const float v0 = w[((long)co * CI + 2 * cip)     * 9 + tap];
    const float v1 = w[((long)co * CI + 2 * cip + 1) * 9 + tap];
    unsigned h, l;
    split2(v0, v1, h, l);
    wio[(long)idx * 2]     = h;
    wio[(long)idx * 2 + 1] = l;
}

// ---------------- zero kernel ----------------
__global__ void zero_kernel(float* __restrict__ p, int n)
{
    const int i = blockIdx.x * blockDim.x + threadIdx.x;
    if (i < n) p[i] = 0.f;
}

// ---------------- conv2/3: implicit-GEMM bf16 3-term, interleaved hi/lo (LDS.64 frags) ----------------
// smem (unsigned words): patch [16 cip][408] (slot=(r*20+c)*2+plane), weights 2 stages
// [16 cip][152] (slot=co*2+plane). Bank-safe: pair-bank = 12*gq + gr (mod 16), injective.
template<bool PAIR_OUT, bool ATT>
__global__ __launch_bounds__(256)
void conv_bf_kernel(const uint2* __restrict__ in, const unsigned* __restrict__ wio,
                    const float* __restrict__ bias,
                    float* __restrict__ outF, uint2* __restrict__ outP,
                    const float* __restrict__ wa, float* __restrict__ lg,
                    int H, int W, int CItot, int COtot, int coBlocks)
{
    const int tid   = threadIdx.x;
    const int warp  = tid >> 5;
    const int lane  = tid & 31;
    const int warpM = warp >> 1;
    const int warpN = warp & 1;
    const int gr    = lane >> 2;
    const int gq    = lane & 3;
    const int b     = blockIdx.z / coBlocks;
    const int co0   = (blockIdx.z % coBlocks) * 64;
    const int x0    = blockIdx.x * 16;
    const int y0    = blockIdx.y * 8;
    const int HP = H >> 1, WP = W >> 1;
    const int CIP = CItot >> 1;

    __shared__ __align__(16) unsigned smemU[11392];   // 45568 B
    unsigned* patch = smemU;                          // 16*408 = 6528 words
    float*    preS  = (float*)smemU;                  // [128][65] epilogue alias

    float acc[2][4][4];
#pragma unroll
    for (int mt = 0; mt < 2; mt++)
#pragma unroll
        for (int nt = 0; nt < 4; nt++)
#pragma unroll
            for (int i = 0; i < 4; i++) acc[mt][nt][i] = 0.f;

    auto issue_w = [&](int stage, int tap, int cip0) {
        unsigned* wS = smemU + 6528 + stage * 2432;
#pragma unroll
        for (int i = 0; i < 2; i++) {
            const int slot = tid + i * 256;           // 0..511
            const int cip = slot >> 5, wi = slot & 31;  // wi: 16B unit = 2 co
            const long src = (((long)tap * CIP + cip0 + cip) * COtot + co0 + wi * 2) * 2;
            cpa16((unsigned)__cvta_generic_to_shared(wS + cip * 152 + wi * 4), wio + src, true);
        }
        cpa_commit();
    };

    for (int ci0 = 0; ci0 < CItot; ci0 += 32) {
        const int cip0 = ci0 >> 1;
        __syncthreads();
        issue_w(0, 0, cip0);
        // patch fill: 16 cip x 10 r x 18 c, single uint2 LDG + STS.64
        for (int idx = tid; idx < 2880; idx += 256) {
            const int cip = idx / 180, rem = idx % 180;
            const int r = rem / 18, c = rem % 18;
            const int y = y0 - 1 + r, x = x0 - 1 + c;
            uint2 v = make_uint2(0u, 0u);
            if (y >= 0 && y < H && x >= 0 && x < W)
                v = __ldg(in + ((long)(b * CIP + cip0 + cip) * H + y) * W + x);
            *(uint2*)(patch + cip * 408 + (r * 20 + c) * 2) = v;
        }
        for (int tap = 0; tap < 9; tap++) {
            cpa_wait0();
            __syncthreads();
            if (tap < 8) issue_w((tap + 1) & 1, tap + 1, cip0);
            const unsigned* wS = smemU + 6528 + (tap & 1) * 2432;
            const int ky = tap / 3, kx = tap % 3;
#pragma unroll
            for (int kb = 0; kb < 2; kb++) {
                unsigned ah[2][4], al[2][4];
#pragma unroll
                for (int mt = 0; mt < 2; mt++) {
                    const int yrow = 2 * warpM + mt + ky;
                    const unsigned* ab = patch + (kb * 8 + gq) * 408 + (yrow * 20 + kx + gr) * 2;
                    uint2 t0 = *(const uint2*)ab;               // (cip gq,   x)
                    uint2 t1 = *(const uint2*)(ab + 16);        // (cip gq,   x+8)
                    uint2 t2 = *(const uint2*)(ab + 4 * 408);   // (cip gq+4, x)
                    uint2 t3 = *(const uint2*)(ab + 4 * 408 + 16);
                    ah[mt][0] = t0.x; al[mt][0] = t0.y;
                    ah[mt][1] = t1.x; al[mt][1] = t1.y;
                    ah[mt][2] = t2.x; al[mt][2] = t2.y;
                    ah[mt][3] = t3.x; al[mt][3] = t3.y;
                }
                unsigned bh[4][2], bl[4][2];
#pragma unroll
                for (int nt = 0; nt < 4; nt++) {
                    const int col = warpN * 32 + nt * 8 + gr;
                    const unsigned* bb = wS + (kb * 8 + gq) * 152 + col * 2;
                    uint2 b0 = *(const uint2*)bb;
                    uint2 b1 = *(const uint2*)(bb + 4 * 152);
                    bh[nt][0] = b0.x; bl[nt][0] = b0.y;
                    bh[nt][1] = b1.x; bl[nt][1] = b1.y;
                }
#pragma unroll
                for (int mt = 0; mt < 2; mt++)
#pragma unroll
                    for (int nt = 0; nt < 4; nt++) {
                        mma_bf16(acc[mt][nt], ah[mt], bh[nt]);
                        mma_bf16(acc[mt][nt], al[mt], bh[nt]);
                        mma_bf16(acc[mt][nt], ah[mt], bl[nt]);
                    }
            }
        }
    }

    // ---- epilogue: stash pre-pool, then pool+bias+relu ----
    __syncthreads();
#pragma unroll
    for (int mt = 0; mt < 2; mt++)
#pragma unroll
        for (int nt = 0; nt < 4; nt++) {
            const int m0 = (2 * warpM + mt) * 16;
            const int cc = warpN * 32 + nt * 8 + 2 * gq;
            const float* ac = acc[mt][nt];
            preS[(m0 + gr) * 65 + cc]         = ac[0];
            preS[(m0 + gr) * 65 + cc + 1]     = ac[1];
            preS[(m0 + gr + 8) * 65 + cc]     = ac[2];
            preS[(m0 + gr + 8) * 65 + cc + 1] = ac[3];
        }
    __syncthreads();

    if (PAIR_OUT) {
        const int COP = COtot >> 1;
        for (int idx = tid; idx < 1024; idx += 256) {
            const int pp = idx & 31;
            const int cop = idx >> 5;
            const int lx = (pp & 7) * 2, ly = (pp >> 3) * 2;
            const int m = ly * 16 + lx;
            const int c0c = 2 * cop;
            float v0 = fmaxf(fmaxf(preS[m * 65 + c0c], preS[(m + 1) * 65 + c0c]),
                             fmaxf(preS[(m + 16) * 65 + c0c], preS[(m + 17) * 65 + c0c]));
            float v1 = fmaxf(fmaxf(preS[m * 65 + c0c + 1], preS[(m + 1) * 65 + c0c + 1]),
                             fmaxf(preS[(m + 16) * 65 + c0c + 1], preS[(m + 17) * 65 + c0c + 1]));
            v0 = fmaxf(v0 + bias[co0 + c0c], 0.f);
            v1 = fmaxf(v1 + bias[co0 + c0c + 1], 0.f);
            const int pxg = (x0 >> 1) + (pp & 7);
            const int pyg = (y0 >> 1) + (pp >> 3);
            if (pxg < WP && pyg < HP) {
                unsigned h, l;
                split2(v0, v1, h, l);
                outP[((long)(b * COP + (co0 >> 1) + cop) * HP + pyg) * WP + pxg] = make_uint2(h, l);
            }
        }
    } else {
        for (int idx = tid; idx < 2048; idx += 256) {
            const int pp = idx & 31;
            const int co = idx >> 5;
            const int lx = (pp & 7) * 2, ly = (pp >> 3) * 2;
            const int m = ly * 16 + lx;
            float v = fmaxf(fmaxf(preS[m * 65 + co], preS[(m + 1) * 65 + co]),
                            fmaxf(preS[(m + 16) * 65 + co], preS[(m + 17) * 65 + co]));
            v = fmaxf(v + bias[co0 + co], 0.f);
            const int pxg = (x0 >> 1) + (pp & 7);
            const int pyg = (y0 >> 1) + (pp >> 3);
            if (pxg < WP && pyg < HP)
                outF[((long)(b * COtot + co0 + co) * HP + pyg) * WP + pxg] = v;
        }
        if (ATT && tid < 64) {
            const int co = tid;
            const float bv = bias[co0 + co];
            float sum = 0.f;
            for (int pp = 0; pp < 32; pp++) {
                const int pxg = (x0 >> 1) + (pp & 7);
                const int pyg = (y0 >> 1) + (pp >> 3);
                if (pxg < WP && pyg < HP) {
                    const int m = (pp >> 3) * 2 * 16 + (pp & 7) * 2;
                    float v = fmaxf(fmaxf(preS[m * 65 + co], preS[(m + 1) * 65 + co]),
                                    fmaxf(preS[(m + 16) * 65 + co], preS[(m + 17) * 65 + co]));
                    v = fmaxf(v + bv, 0.f);
                    sum += v * __ldg(wa + pyg * WP + pxg);
                }
            }
            atomicAdd(&lg[b * NF_ + co0 + co], sum);
        }
    }
}

// ---------------- softmax over features (ba omitted: constant shift cancels) ----------------
__global__ void attn_softmax_kernel(const float* __restrict__ logits, float* __restrict__ att)
{
    __shared__ float sh[128];
    const int b = blockIdx.x, n = threadIdx.x;
    const float v = logits[b * NF_ + n];
    sh[n] = v;
    __syncthreads();
    for (int off = 64; off > 0; off >>= 1) {
        if (n < off) sh[n] = fmaxf(sh[n], sh[n + off]);
        __syncthreads();
    }
    const float mx = sh[0];
    __syncthreads();
    const float e = expf(v - mx);
    sh[n] = e;
    __syncthreads();
    for (int off = 64; off > 0; off >>= 1) {
        if (n < off) sh[n] += sh[n + off];
        __syncthreads();
    }
    att[b * NF_ + n] = e / sh[0];
}

// ---------------- init output with bias ----------------
__global__ void init_bias_kernel(float* __restrict__ C, const float* __restrict__ bias, int N, int M)
{
    const int i = blockIdx.x * blockDim.x + threadIdx.x;
    if (i < M * N) C[i] = bias[i % N];
}

// ---------------- bf16 3-term skinny GEMM, cp.async 3-stage pipeline ----------------
#define GSTAGES 3
template<bool ARELU, bool ASCALE, bool ATOMIC, bool ORELU>
__global__ __launch_bounds__(128)
void gemm_bf_kernel(const float* __restrict__ A, long strideA_n, long lda,
                    const float* __restrict__ scale,
                    const float* __restrict__ W, long strideW_n,
                    const float* __restrict__ bias, long strideBias_n,
                    float* __restrict__ C, long strideC_n, long ldc,
                    int K, int N)
{
    const int n    = blockIdx.y;
    const int j0   = blockIdx.x * 64;
    const int tid  = threadIdx.x;
    const int warp = tid >> 5;
    const int lane = tid & 31;
    const int gr   = lane >> 2;
    const int gq   = lane & 3;

    A += (long)n * strideA_n;
    W += (long)n * strideW_n;
    C += (long)n * strideC_n;

    const int kchunks = (K + 31) >> 5;
    const int per = (kchunks + gridDim.z - 1) / gridDim.z;
    const int c0 = blockIdx.z * per;
    const int c1 = min(kchunks, c0 + per);

    __shared__ __align__(16) float Wst[GSTAGES][32][68];
    __shared__ __align__(16) float Ast[GSTAGES][32][36];
    __shared__ float ssc[32];

    if (ASCALE && tid < 32) ssc[tid] = scale[(long)tid * NF_ + n];

    const bool vecN = ((N & 3) == 0);

    auto issue = [&](int stage, int cc) {
        const int k0 = cc << 5;
#pragma unroll
        for (int i = 0; i < 2; i++) {
            const int slot = tid + i * 128;
            const int m = slot >> 3, q = slot & 7;
            const int kk = k0 + q * 4;
            unsigned dst = (unsigned)__cvta_generic_to_shared(&Ast[stage][m][q * 4]);
            cpa16(dst, A + (long)m * lda + kk, kk < K);
        }
        if (vecN) {
#pragma unroll
            for (int i = 0; i < 4; i++) {
                const int slot = tid + i * 128;
                const int kr = slot >> 4, c4 = (slot & 15) * 4;
                const int kk = k0 + kr, jj = j0 + c4;
                unsigned dst = (unsigned)__cvta_generic_to_shared(&Wst[stage][kr][c4]);
                cpa16(dst, W + (long)kk * N + jj, (kk < K) && (jj < N));
            }
        } else {
#pragma unroll
            for (int i = 0; i < 16; i++) {
                const int slot = tid + i * 128;
                const int kr = slot >> 6, nn = slot & 63;
                const int kk = k0 + kr, jj = j0 + nn;
                const bool ok = (kk < K) && (jj < N);
                unsigned dst = (unsigned)__cvta_generic_to_shared(&Wst[stage][kr][nn]);
                cpa4(dst, ok ? (W + (long)kk * N + jj) : W, ok);
            }
        }
        cpa_commit();
    };

    float acc[2][2][4];
#pragma unroll
    for (int mt = 0; mt < 2; mt++)
#pragma unroll
        for (int nt = 0; nt < 2; nt++)
#pragma unroll
            for (int i = 0; i < 4; i++) acc[mt][nt][i] = 0.f;

    for (int p = 0; p < GSTAGES - 1; p++) {
        if (c0 + p < c1) issue(p, c0 + p);
        else cpa_commit();
    }

    for (int cc = c0; cc < c1; cc++) {
        cpa_wait1();
        __syncthreads();
        const int t = cc - c0;
        if (cc + GSTAGES - 1 < c1) issue((t + GSTAGES - 1) % GSTAGES, cc + GSTAGES - 1);
        else cpa_commit();

        const int s = t % GSTAGES;
        const float* Ab = &Ast[s][0][0];
        const float* Wb = &Wst[s][0][0];
#pragma unroll
        for (int kb = 0; kb < 2; kb++) {
            const int k16 = kb * 16;
            unsigned ah[2][4], al[2][4], bh[2][2], bl[2][2];
#pragma unroll
            for (int mt = 0; mt < 2; mt++) {
                const int m0 = mt * 16;
                float2 v0 = *(const float2*)(Ab + (m0 + gr) * 36 + k16 + 2 * gq);
                float2 v1 = *(const float2*)(Ab + (m0 + gr + 8) * 36 + k16 + 2 * gq);
                float2 v2 = *(const float2*)(Ab + (m0 + gr) * 36 + k16 + 8 + 2 * gq);
                float2 v3 = *(const float2*)(Ab + (m0 + gr + 8) * 36 + k16 + 8 + 2 * gq);
                if (ARELU) {
                    v0.x = fmaxf(v0.x, 0.f); v0.y = fmaxf(v0.y, 0.f);
                    v1.x = fmaxf(v1.x, 0.f); v1.y = fmaxf(v1.y, 0.f);
                    v2.x = fmaxf(v2.x, 0.f); v2.y = fmaxf(v2.y, 0.f);
                    v3.x = fmaxf(v3.x, 0.f); v3.y = fmaxf(v3.y, 0.f);
                }
                if (ASCALE) {
                    const float s0 = ssc[m0 + gr], s1 = ssc[m0 + gr + 8];
                    v0.x *= s0; v0.y *= s0; v2.x *= s0; v2.y *= s0;
                    v1.x *= s1; v1.y *= s1; v3.x *= s1; v3.y *= s1;
                }
                split2(v0.x, v0.y, ah[mt][0], al[mt][0]);
                split2(v1.x, v1.y, ah[mt][1], al[mt][1]);
                split2(v2.x, v2.y, ah[mt][2], al[mt][2]);
                split2(v3.x, v3.y, ah[mt][3], al[mt][3]);
            }
#pragma unroll
            for (int nt = 0; nt < 2; nt++) {
                const int nc = warp * 16 + nt * 8 + gr;
                float w0 = Wb[(k16 + 2 * gq) * 68 + nc];
                float w1 = Wb[(k16 + 2 * gq + 1) * 68 + nc];
                split2(w0, w1, bh[nt][0], bl[nt][0]);
                w0 = Wb[(k16 + 8 + 2 * gq) * 68 + nc];
                w1 = Wb[(k16 + 9 + 2 * gq) * 68 + nc];
                split2(w0, w1, bh[nt][1], bl[nt][1]);
            }
#pragma unroll
            for (int mt = 0; mt < 2; mt++)
#pragma unroll
                for (int nt = 0; nt < 2; nt++) {
                    mma_bf16(acc[mt][nt], ah[mt], bh[nt]);
                    mma_bf16(acc[mt][nt], al[mt], bh[nt]);
                    mma_bf16(acc[mt][nt], ah[mt], bl[nt]);
                }
        }
        __syncthreads();
    }

#pragma unroll
    for (int mt = 0; mt < 2; mt++) {
#pragma unroll
        for (int nt = 0; nt < 2; nt++) {
            const float* ac = acc[mt][nt];
            const int row0 = mt * 16 + gr;
            const int col  = j0 + warp * 16 + nt * 8 + 2 * gq;
            if (ATOMIC) {
                if (col < N) {
                    atomicAdd(&C[(long)row0 * ldc + col], ac[0]);
                    atomicAdd(&C[(long)(row0 + 8) * ldc + col], ac[2]);
                }
                if (col + 1 < N) {
                    atomicAdd(&C[(long)row0 * ldc + col + 1], ac[1]);
                    atomicAdd(&C[(long)(row0 + 8) * ldc + col + 1], ac[3]);
                }
            } else {
                const float* bn = bias + (long)n * strideBias_n;
#pragma unroll
                for (int h = 0; h < 2; h++) {
                    const int j = col + h;
                    if (j < N) {
                        float v0 = ac[h]     + bn[j];
                        float v1 = ac[h + 2] + bn[j];
                        if (ORELU) { v0 = fmaxf(v0, 0.f); v1 = fmaxf(v1, 0.f); }
                        C[(long)row0 * ldc + j] = v0;
                        C[(long)(row0 + 8) * ldc + j] = v1;
                    }
                }
            }
        }
    }
}

// ---------------- launch ----------------
extern "C" void kernel_launch(void* const* d_in, const int* in_sizes, int n_in,
                              void* d_out, int out_size)
{
    const float* x   = (const float*)d_in[0];
    const float* cw1 = (const float*)d_in[1];
    const float* cb1 = (const float*)d_in[2];
    const float* cw2 = (const float*)d_in[3];
    const float* cb2 = (const float*)d_in[4];
    const float* cw3 = (const float*)d_in[5];
    const float* cb3 = (const float*)d_in[6];
    const float* wa  = (const float*)d_in[7];
    const float* ew1 = (const float*)d_in[9];
    const float* eb1 = (const float*)d_in[10];
    const float* ew2 = (const float*)d_in[11];
    const float* eb2 = (const float*)d_in[12];
    const float* ew3 = (const float*)d_in[13];
    const float* eb3 = (const float*)d_in[14];
    const float* fw1 = (const float*)d_in[15];
    const float* fb1 = (const float*)d_in[16];
    const float* fw2 = (const float*)d_in[17];
    const float* fb2 = (const float*)d_in[18];
    const float* fw3 = (const float*)d_in[19];
    const float* fb3 = (const float*)d_in[20];
    float* out = (float*)d_out;

    float *f, *lg, *att, *h1, *h2, *e, *g1, *g2;
    uint2 *p1, *p2;
    unsigned *w2i, *w3i;
    cudaGetSymbolAddress((void**)&p1,  g_p1);
    cudaGetSymbolAddress((void**)&p2,  g_p2);
    cudaGetSymbolAddress((void**)&f,   g_f);
    cudaGetSymbolAddress((void**)&lg,  g_lg);
    cudaGetSymbolAddress((void**)&att, g_at);
    cudaGetSymbolAddress((void**)&h1,  g_h1);
    cudaGetSymbolAddress((void**)&h2,  g_h2);
    cudaGetSymbolAddress((void**)&e,   g_e);
    cudaGetSymbolAddress((void**)&g1,  g_g1);
    cudaGetSymbolAddress((void**)&g2,  g_g2);
    cudaGetSymbolAddress((void**)&w2i, g_w2i);
    cudaGetSymbolAddress((void**)&w3i, g_w3i);

    conv_wprep_kernel<<<36, 256>>>(cw2, w2i, 32, 64);
    conv_wprep_kernel<<<144, 256>>>(cw3, w3i, 64, 128);

    // CNN stem (interleaved pair-plane dataflow)
    conv1_kernel<<<dim3(49, 4, 32), 256>>>(x, cw1, cb1, p1);
    conv_bf_kernel<true, false><<<dim3(7, 14, 32), 256>>>(
        p1, w2i, cb2, nullptr, p2, nullptr, nullptr, 112, 112, 32, 64, 1);
    zero_kernel<<<16, 256>>>(lg, 32 * 128);
    conv_bf_kernel<false, true><<<dim3(4, 7, 64), 256>>>(
        p2, w3i, cb3, f, nullptr, wa, lg, 56, 56, 64, 128, 2);

    attn_softmax_kernel<<<32, 128>>>(lg, att);

    // experts
    gemm_bf_kernel<false, true, false, true><<<dim3(13, 128, 1), 128>>>(
        f, 784L, 128L * 784, att, ew1, 784L * 784, eb1, 784L, h1, 784L, 128L * 784, 784, 784);
    gemm_bf_kernel<false, false, false, true><<<dim3(7, 128, 1), 128>>>(
        h1, 784L, 128L * 784, nullptr, ew2, 784L * 392, eb2, 392L, h2, 392L, 128L * 392, 784, 392);
    gemm_bf_kernel<false, false, false, true><<<dim3(1, 128, 1), 128>>>(
        h2, 392L, 128L * 392, nullptr, ew3, 392L * 64, eb3, 64L, e, 64L, 8192L, 392, 64);

    // head: deeper k-splits to fill 148 SMs
    init_bias_kernel<<<1024, 256>>>(g1, fb1, FIN_, B_);
    gemm_bf_kernel<false, false, true, false><<<dim3(128, 1, 4), 128>>>(
        e, 0L, 8192L, nullptr, fw1, 0L, nullptr, 0L, g1, 0L, 8192L, 8192, 8192);

    init_bias_kernel<<<512, 256>>>(g2, fb2, FHID_, B_);
    gemm_bf_kernel<true, false, true, false><<<dim3(64, 1, 6), 128>>>(
        g1, 0L, 8192L, nullptr, fw2, 0L, nullptr, 0L, g2, 0L, 4096L, 8192, 4096);

    init_bias_kernel<<<7, 256>>>(out, fb3, OUT_, B_);
    gemm_bf_kernel<true, false, true, false><<<dim3(1, 1, 32), 128>>>(
        g2, 0L, 4096L, nullptr, fw3, 0L, nullptr, 0L, out, 0L, 53L, 4096, 53);
}

// round 15
// speedup vs baseline: 1.0858x; 1.0858x over previous
#include <cuda_runtime.h>
#include <math.h>

#define B_   32
#define NF_  128
#define FLAT_ 784
#define HID2_ 392
#define EO_  64
#define FIN_ 8192
#define FHID_ 4096
#define OUT_ 53

// ---------------- scratch (static device allocations) ----------------
__device__ unsigned g_p1h[32 * 16 * 112 * 112];
__device__ unsigned g_p1l[32 * 16 * 112 * 112];
__device__ unsigned g_p2h[32 * 32 * 56 * 56];
__device__ unsigned g_p2l[32 * 32 * 56 * 56];
__device__ float g_f [32 * 128 * 28 * 28];
__device__ float g_lg[32 * 128];
__device__ float g_at[32 * 128];
__device__ float g_h1[32 * 128 * 784];
__device__ float g_h2[32 * 128 * 392];
__device__ float g_e [32 * 8192];
__device__ float g_g1[32 * 8192];
__device__ float g_g2[32 * 4096];
__device__ unsigned g_wh2[9 * 16 * 64];
__device__ unsigned g_wl2[9 * 16 * 64];
__device__ unsigned g_wh3[9 * 32 * 128];
__device__ unsigned g_wl3[9 * 32 * 128];

// ---------------- bf16 split helpers ----------------
__device__ __forceinline__ void split2(float x, float y, unsigned& h, unsigned& l) {
    asm("cvt.rn.bf16x2.f32 %0, %1, %2;" : "=r"(h) : "f"(y), "f"(x));
    float rx = x - __uint_as_float(h << 16);
    float ry = y - __uint_as_float(h & 0xffff0000u);
    asm("cvt.rn.bf16x2.f32 %0, %1, %2;" : "=r"(l) : "f"(ry), "f"(rx));
}
__device__ __forceinline__ void mma_bf16(float* c, const unsigned* a, const unsigned* b) {
    asm("mma.sync.aligned.m16n8k16.row.col.f32.bf16.bf16.f32 "
        "{%0,%1,%2,%3}, {%4,%5,%6,%7}, {%8,%9}, {%0,%1,%2,%3};"
        : "+f"(c[0]), "+f"(c[1]), "+f"(c[2]), "+f"(c[3])
        : "r"(a[0]), "r"(a[1]), "r"(a[2]), "r"(a[3]), "r"(b[0]), "r"(b[1]));
}

// ---------------- cp.async helpers ----------------
__device__ __forceinline__ void cpa16(unsigned dst, const void* src, bool pred) {
    int b = pred ? 16 : 0;
    asm volatile("cp.async.cg.shared.global [%0], [%1], 16, %2;" :: "r"(dst), "l"(src), "r"(b));
}
__device__ __forceinline__ void cpa4(unsigned dst, const void* src, bool pred) {
    int b = pred ? 4 : 0;
    asm volatile("cp.async.ca.shared.global [%0], [%1], 4, %2;" :: "r"(dst), "l"(src), "r"(b));
}
__device__ __forceinline__ void cpa_commit() {
    asm volatile("cp.async.commit_group;" ::: "memory");
}
__device__ __forceinline__ void cpa_wait0() {
    asm volatile("cp.async.wait_group 0;" ::: "memory");
}
__device__ __forceinline__ void cpa_wait1() {
    asm volatile("cp.async.wait_group 1;" ::: "memory");
}

// ---------------- conv1: fp32 conv3x3+bias+relu+pool -> bf16 pair planes ----------------
__global__ __launch_bounds__(256)
void conv1_kernel(const float* __restrict__ in, const float* __restrict__ w,
                  const float* __restrict__ bias,
                  unsigned* __restrict__ outH, unsigned* __restrict__ outL)
{
    const int CI = 3, CO_T = 8, H = 224, W = 224;
    __shared__ float sw[CO_T * CI * 9];
    const int tid = threadIdx.x;
    const int co0 = blockIdx.y * CO_T;
    const int b   = blockIdx.z;

    for (int i = tid; i < CO_T * CI * 9; i += 256)
        sw[i] = w[(long)co0 * CI * 9 + i];
    __syncthreads();

    const int HP = 112, WP = 112;
    const int p = blockIdx.x * 256 + tid;
    const int py = p / WP, px = p % WP;
    const int y0 = 2 * py, x0 = 2 * px;

    float acc[CO_T][4];
#pragma unroll
    for (int t = 0; t < CO_T; t++)
        acc[t][0] = acc[t][1] = acc[t][2] = acc[t][3] = 0.f;

    for (int ci = 0; ci < CI; ci++) {
        const float* ip = in + ((long)(b * CI + ci)) * H * W;
        float v[4][4];
#pragma unroll
        for (int r = 0; r < 4; r++) {
            const int yy = y0 - 1 + r;
            const bool yok = (yy >= 0) && (yy < H);
#pragma unroll
            for (int c = 0; c < 4; c++) {
                const int xx = x0 - 1 + c;
                const bool ok = yok && (xx >= 0) && (xx < W);
                v[r][c] = ok ? __ldg(ip + (long)yy * W + xx) : 0.f;
            }
        }
        const float* swc = sw + ci * 9;
#pragma unroll
        for (int t = 0; t < CO_T; t++) {
            const float* wt = swc + t * CI * 9;
#pragma unroll
            for (int ky = 0; ky < 3; ky++)
#pragma unroll
                for (int kx = 0; kx < 3; kx++) {
                    const float wv = wt[ky * 3 + kx];
                    acc[t][0] = fmaf(v[ky    ][kx    ], wv, acc[t][0]);
                    acc[t][1] = fmaf(v[ky    ][kx + 1], wv, acc[t][1]);
                    acc[t][2] = fmaf(v[ky + 1][kx    ], wv, acc[t][2]);
                    acc[t][3] = fmaf(v[ky + 1][kx + 1], wv, acc[t][3]);
                }
        }
    }
    const int cop0 = co0 >> 1;
#pragma unroll
    for (int t = 0; t < 4; t++) {
        float v0 = fmaxf(fmaxf(acc[2*t][0], acc[2*t][1]), fmaxf(acc[2*t][2], acc[2*t][3])) + bias[co0 + 2*t];
        float v1 = fmaxf(fmaxf(acc[2*t+1][0], acc[2*t+1][1]), fmaxf(acc[2*t+1][2], acc[2*t+1][3])) + bias[co0 + 2*t + 1];
        v0 = fmaxf(v0, 0.f); v1 = fmaxf(v1, 0.f);
        unsigned h, l;
        split2(v0, v1, h, l);
        const long off = ((long)(b * 16 + cop0 + t) * HP + py) * WP + px;
        outH[off] = h;
        outL[off] = l;
    }
}

// ---------------- conv weight prep ----------------
__global__ void conv_wprep_kernel(const float* __restrict__ w,
                                  unsigned* __restrict__ whi, unsigned* __restrict__ wlo,
                                  int CI, int CO)
{
    const int idx = blockIdx.x * blockDim.x + threadIdx.x;
    const int CIP = CI >> 1;
    const int total = 9 * CIP * CO;
    if (idx >= total) return;
    const int co  = idx % CO;
    const int rest = idx / CO;
    const int cip = rest % CIP;
    const int tap = rest / CIP;
    const float v0 = w[((long)co * CI + 2 * cip)     * 9 + tap];
    const float v1 = w[((long)co * CI + 2 * cip + 1) * 9 + tap];
    unsigned h, l;
    split2(v0, v1, h, l);
    whi[idx] = h;
    wlo[idx] = l;
}

// ---------------- zero kernel ----------------
__global__ void zero_kernel(float* __restrict__ p, int n)
{
    const int i = blockIdx.x * blockDim.x + threadIdx.x;
    if (i < n) p[i] = 0.f;
}

// ---------------- conv2/3: implicit-GEMM bf16 3-term from pair planes (R13 layout) ----------------
template<bool PAIR_OUT, bool ATT>
__global__ __launch_bounds__(256)
void conv_bf_kernel(const unsigned* __restrict__ inH, const unsigned* __restrict__ inL,
                    const unsigned* __restrict__ whi, const unsigned* __restrict__ wlo,
                    const float* __restrict__ bias,
                    float* __restrict__ outF, unsigned* __restrict__ outH, unsigned* __restrict__ outL,
                    const float* __restrict__ wa, float* __restrict__ lg,
                    int H, int W, int CItot, int COtot, int coBlocks)
{
    const int tid   = threadIdx.x;
    const int warp  = tid >> 5;
    const int lane  = tid & 31;
    const int warpM = warp >> 1;
    const int warpN = warp & 1;
    const int gr    = lane >> 2;
    const int gq    = lane & 3;
    const int b     = blockIdx.z / coBlocks;
    const int co0   = (blockIdx.z % coBlocks) * 64;
    const int x0    = blockIdx.x * 16;
    const int y0    = blockIdx.y * 8;
    const int HP = H >> 1, WP = W >> 1;
    const int CIP = CItot >> 1;

    __shared__ __align__(16) unsigned char raw[44032];
    unsigned* pH  = (unsigned*)raw;                  // [16 cip][10][20] stride 200
    unsigned* pL  = (unsigned*)(raw + 12800);
    unsigned* wHs0 = (unsigned*)(raw + 25600);
    unsigned* wHs1 = (unsigned*)(raw + 30208);
    unsigned* wLs0 = (unsigned*)(raw + 34816);
    unsigned* wLs1 = (unsigned*)(raw + 39424);
    float*    preS = (float*)raw;                    // [128][65] epilogue alias

    float acc[2][4][4];
#pragma unroll
    for (int mt = 0; mt < 2; mt++)
#pragma unroll
        for (int nt = 0; nt < 4; nt++)
#pragma unroll
            for (int i = 0; i < 4; i++) acc[mt][nt][i] = 0.f;

    auto issue_w = [&](int stage, int tap, int cip0) {
        unsigned* wH = stage ? wHs1 : wHs0;
        unsigned* wL = stage ? wLs1 : wLs0;
        const int cip = tid >> 4, c4 = (tid & 15) * 4;
        const long src = ((long)tap * CIP + cip0 + cip) * COtot + co0 + c4;
        cpa16((unsigned)__cvta_generic_to_shared(wH + cip * 72 + c4), whi + src, true);
        cpa16((unsigned)__cvta_generic_to_shared(wL + cip * 72 + c4), wlo + src, true);
        cpa_commit();
    };

    for (int ci0 = 0; ci0 < CItot; ci0 += 32) {
        const int cip0 = ci0 >> 1;
        __syncthreads();
        issue_w(0, 0, cip0);
        for (int idx = tid; idx < 2880; idx += 256) {
            const int cip = idx / 180, rem = idx % 180;
            const int r = rem / 18, c = rem % 18;
            const int y = y0 - 1 + r, x = x0 - 1 + c;
            unsigned h = 0u, l = 0u;
            if (y >= 0 && y < H && x >= 0 && x < W) {
                const long off = ((long)(b * CIP + cip0 + cip) * H + y) * W + x;
                h = __ldg(inH + off);
                l = __ldg(inL + off);
            }
            pH[cip * 200 + r * 20 + c] = h;
            pL[cip * 200 + r * 20 + c] = l;
        }
        for (int tap = 0; tap < 9; tap++) {
            cpa_wait0();
            __syncthreads();
            if (tap < 8) issue_w((tap + 1) & 1, tap + 1, cip0);
            const unsigned* wH = (tap & 1) ? wHs1 : wHs0;
            const unsigned* wL = (tap & 1) ? wLs1 : wLs0;
            const int ky = tap / 3, kx = tap % 3;
#pragma unroll
            for (int kb = 0; kb < 2; kb++) {
                unsigned ah[2][4], al[2][4];
#pragma unroll
                for (int mt = 0; mt < 2; mt++) {
                    const int yrow = 2 * warpM + mt + ky;
                    const unsigned* bh_ = pH + (kb * 8 + gq) * 200 + yrow * 20 + kx;
                    const unsigned* bl_ = pL + (kb * 8 + gq) * 200 + yrow * 20 + kx;
                    ah[mt][0] = bh_[gr];       ah[mt][1] = bh_[gr + 8];
                    ah[mt][2] = bh_[800 + gr]; ah[mt][3] = bh_[800 + gr + 8];
                    al[mt][0] = bl_[gr];       al[mt][1] = bl_[gr + 8];
                    al[mt][2] = bl_[800 + gr]; al[mt][3] = bl_[800 + gr + 8];
                }
                unsigned bh[4][2], bl[4][2];
#pragma unroll
                for (int nt = 0; nt < 4; nt++) {
                    const int col = warpN * 32 + nt * 8 + gr;
                    bh[nt][0] = wH[(kb * 8 + gq) * 72 + col];
                    bh[nt][1] = wH[(kb * 8 + gq + 4) * 72 + col];
                    bl[nt][0] = wL[(kb * 8 + gq) * 72 + col];
                    bl[nt][1] = wL[(kb * 8 + gq + 4) * 72 + col];
                }
#pragma unroll
                for (int mt = 0; mt < 2; mt++)
#pragma unroll
                    for (int nt = 0; nt < 4; nt++) {
                        mma_bf16(acc[mt][nt], ah[mt], bh[nt]);
                        mma_bf16(acc[mt][nt], al[mt], bh[nt]);
                        mma_bf16(acc[mt][nt], ah[mt], bl[nt]);
                    }
            }
        }
    }

    __syncthreads();
#pragma unroll
    for (int mt = 0; mt < 2; mt++)
#pragma unroll
        for (int nt = 0; nt < 4; nt++) {
            const int m0 = (2 * warpM + mt) * 16;
            const int cc = warpN * 32 + nt * 8 + 2 * gq;
            const float* ac = acc[mt][nt];
            preS[(m0 + gr) * 65 + cc]         = ac[0];
            preS[(m0 + gr) * 65 + cc + 1]     = ac[1];
            preS[(m0 + gr + 8) * 65 + cc]     = ac[2];
            preS[(m0 + gr + 8) * 65 + cc + 1] = ac[3];
        }
    __syncthreads();

    if (PAIR_OUT) {
        const int COP = COtot >> 1;
        for (int idx = tid; idx < 1024; idx += 256) {
            const int pp = idx & 31;
            const int cop = idx >> 5;
            const int lx = (pp & 7) * 2, ly = (pp >> 3) * 2;
            const int m = ly * 16 + lx;
            const int c0c = 2 * cop;
            float v0 = fmaxf(fmaxf(preS[m * 65 + c0c], preS[(m + 1) * 65 + c0c]),
                             fmaxf(preS[(m + 16) * 65 + c0c], preS[(m + 17) * 65 + c0c]));
            float v1 = fmaxf(fmaxf(preS[m * 65 + c0c + 1], preS[(m + 1) * 65 + c0c + 1]),
                             fmaxf(preS[(m + 16) * 65 + c0c + 1], preS[(m + 17) * 65 + c0c + 1]));
            v0 = fmaxf(v0 + bias[co0 + c0c], 0.f);
            v1 = fmaxf(v1 + bias[co0 + c0c + 1], 0.f);
            const int pxg = (x0 >> 1) + (pp & 7);
            const int pyg = (y0 >> 1) + (pp >> 3);
            if (pxg < WP && pyg < HP) {
                unsigned h, l;
                split2(v0, v1, h, l);
                const long off = ((long)(b * COP + (co0 >> 1) + cop) * HP + pyg) * WP + pxg;
                outH[off] = h;
                outL[off] = l;
            }
        }
    } else {
        for (int idx = tid; idx < 2048; idx += 256) {
            const int pp = idx & 31;
            const int co = idx >> 5;
            const int lx = (pp & 7) * 2, ly = (pp >> 3) * 2;
            const int m = ly * 16 + lx;
            float v = fmaxf(fmaxf(preS[m * 65 + co], preS[(m + 1) * 65 + co]),
                            fmaxf(preS[(m + 16) * 65 + co], preS[(m + 17) * 65 + co]));
            v = fmaxf(v + bias[co0 + co], 0.f);
            const int pxg = (x0 >> 1) + (pp & 7);
            const int pyg = (y0 >> 1) + (pp >> 3);
            if (pxg < WP && pyg < HP)
                outF[((long)(b * COtot + co0 + co) * HP + pyg) * WP + pxg] = v;
        }
        if (ATT && tid < 64) {
            const int co = tid;
            const float bv = bias[co0 + co];
            float sum = 0.f;
            for (int pp = 0; pp < 32; pp++) {
                const int pxg = (x0 >> 1) + (pp & 7);
                const int pyg = (y0 >> 1) + (pp >> 3);
                if (pxg < WP && pyg < HP) {
                    const int m = (pp >> 3) * 2 * 16 + (pp & 7) * 2;
                    float v = fmaxf(fmaxf(preS[m * 65 + co], preS[(m + 1) * 65 + co]),
                                    fmaxf(preS[(m + 16) * 65 + co], preS[(m + 17) * 65 + co]));
                    v = fmaxf(v + bv, 0.f);
                    sum += v * __ldg(wa + pyg * WP + pxg);
                }
            }
            atomicAdd(&lg[b * NF_ + co0 + co], sum);
        }
    }
}

// ---------------- softmax over features (ba omitted: constant shift cancels) ----------------
__global__ void attn_softmax_kernel(const float* __restrict__ logits, float* __restrict__ att)
{
    __shared__ float sh[128];
    const int b = blockIdx.x, n = threadIdx.x;
    const float v = logits[b * NF_ + n];
    sh[n] = v;
    __syncthreads();
    for (int off = 64; off > 0; off >>= 1) {
        if (n < off) sh[n] = fmaxf(sh[n], sh[n + off]);
        __syncthreads();
    }
    const float mx = sh[0];
    __syncthreads();
    const float e = expf(v - mx);
    sh[n] = e;
    __syncthreads();
    for (int off = 64; off > 0; off >>= 1) {
        if (n < off) sh[n] += sh[n + off];
        __syncthreads();
    }
    att[b * NF_ + n] = e / sh[0];
}

// ---------------- init output with bias ----------------
__global__ void init_bias_kernel(float* __restrict__ C, const float* __restrict__ bias, int N, int M)
{
    const int i = blockIdx.x * blockDim.x + threadIdx.x;
    if (i < M * N) C[i] = bias[i % N];
}

// ---------------- bf16 3-term skinny GEMM, cp.async 3-stage pipeline ----------------
#define GSTAGES 3
template<bool ARELU, bool ASCALE, bool ATOMIC, bool ORELU>
__global__ __launch_bounds__(128)
void gemm_bf_kernel(const float* __restrict__ A, long strideA_n, long lda,
                    const float* __restrict__ scale,
                    const float* __restrict__ W, long strideW_n,
                    const float* __restrict__ bias, long strideBias_n,
                    float* __restrict__ C, long strideC_n, long ldc,
                    int K, int N)
{
    const int n    = blockIdx.y;
    const int j0   = blockIdx.x * 64;
    const int tid  = threadIdx.x;
    const int warp = tid >> 5;
    const int lane = tid & 31;
    const int gr   = lane >> 2;
    const int gq   = lane & 3;

    A += (long)n * strideA_n;
    W += (long)n * strideW_n;
    C += (long)n * strideC_n;

    const int kchunks = (K + 31) >> 5;
    const int per = (kchunks + gridDim.z - 1) / gridDim.z;
    const int c0 = blockIdx.z * per;
    const int c1 = min(kchunks, c0 + per);

    __shared__ __align__(16) float Wst[GSTAGES][32][68];
    __shared__ __align__(16) float Ast[GSTAGES][32][36];
    __shared__ float ssc[32];

    if (ASCALE && tid < 32) ssc[tid] = scale[(long)tid * NF_ + n];

    const bool vecN = ((N & 3) == 0);

    auto issue = [&](int stage, int cc) {
        const int k0 = cc << 5;
#pragma unroll
        for (int i = 0; i < 2; i++) {
            const int slot = tid + i * 128;
            const int m = slot >> 3, q = slot & 7;
            const int kk = k0 + q * 4;
            unsigned dst = (unsigned)__cvta_generic_to_shared(&Ast[stage][m][q * 4]);
            cpa16(dst, A + (long)m * lda + kk, kk < K);
        }
        if (vecN) {
#pragma unroll
            for (int i = 0; i < 4; i++) {
                const int slot = tid + i * 128;
                const int kr = slot >> 4, c4 = (slot & 15) * 4;
                const int kk = k0 + kr, jj = j0 + c4;
                unsigned dst = (unsigned)__cvta_generic_to_shared(&Wst[stage][kr][c4]);
                cpa16(dst, W + (long)kk * N + jj, (kk < K) && (jj < N));
            }
        } else {
#pragma unroll
            for (int i = 0; i < 16; i++) {
                const int slot = tid + i * 128;
                const int kr = slot >> 6, nn = slot & 63;
                const int kk = k0 + kr, jj = j0 + nn;
                const bool ok = (kk < K) && (jj < N);
                unsigned dst = (unsigned)__cvta_generic_to_shared(&Wst[stage][kr][nn]);
                cpa4(dst, ok ? (W + (long)kk * N + jj) : W, ok);
            }
        }
        cpa_commit();
    };

    float acc[2][2][4];
#pragma unroll
    for (int mt = 0; mt < 2; mt++)
#pragma unroll
        for (int nt = 0; nt < 2; nt++)
#pragma unroll
            for (int i = 0; i < 4; i++) acc[mt][nt][i] = 0.f;

    for (int p = 0; p < GSTAGES - 1; p++) {
        if (c0 + p < c1) issue(p, c0 + p);
        else cpa_commit();
    }

    for (int cc = c0; cc < c1; cc++) {
        cpa_wait1();
        __syncthreads();
        const int t = cc - c0;
        if (cc + GSTAGES - 1 < c1) issue((t + GSTAGES - 1) % GSTAGES, cc + GSTAGES - 1);
        else cpa_commit();

        const int s = t % GSTAGES;
        const float* Ab = &Ast[s][0][0];
        const float* Wb = &Wst[s][0][0];
#pragma unroll
        for (int kb = 0; kb < 2; kb++) {
            const int k16 = kb * 16;
            unsigned ah[2][4], al[2][4], bh[2][2], bl[2][2];
#pragma unroll
            for (int mt = 0; mt < 2; mt++) {
                const int m0 = mt * 16;
                float2 v0 = *(const float2*)(Ab + (m0 + gr) * 36 + k16 + 2 * gq);
                float2 v1 = *(const float2*)(Ab + (m0 + gr + 8) * 36 + k16 + 2 * gq);
                float2 v2 = *(const float2*)(Ab + (m0 + gr) * 36 + k16 + 8 + 2 * gq);
                float2 v3 = *(const float2*)(Ab + (m0 + gr + 8) * 36 + k16 + 8 + 2 * gq);
                if (ARELU) {
                    v0.x = fmaxf(v0.x, 0.f); v0.y = fmaxf(v0.y, 0.f);
                    v1.x = fmaxf(v1.x, 0.f); v1.y = fmaxf(v1.y, 0.f);
                    v2.x = fmaxf(v2.x, 0.f); v2.y = fmaxf(v2.y, 0.f);
                    v3.x = fmaxf(v3.x, 0.f); v3.y = fmaxf(v3.y, 0.f);
                }
                if (ASCALE) {
                    const float s0 = ssc[m0 + gr], s1 = ssc[m0 + gr + 8];
                    v0.x *= s0; v0.y *= s0; v2.x *= s0; v2.y *= s0;
                    v1.x *= s1; v1.y *= s1; v3.x *= s1; v3.y *= s1;
                }
                split2(v0.x, v0.y, ah[mt][0], al[mt][0]);
                split2(v1.x, v1.y, ah[mt][1], al[mt][1]);
                split2(v2.x, v2.y, ah[mt][2], al[mt][2]);
                split2(v3.x, v3.y, ah[mt][3], al[mt][3]);
            }
#pragma unroll
            for (int nt = 0; nt < 2; nt++) {
                const int nc = warp * 16 + nt * 8 + gr;
                float w0 = Wb[(k16 + 2 * gq) * 68 + nc];
                float w1 = Wb[(k16 + 2 * gq + 1) * 68 + nc];
                split2(w0, w1, bh[nt][0], bl[nt][0]);
                w0 = Wb[(k16 + 8 + 2 * gq) * 68 + nc];
                w1 = Wb[(k16 + 9 + 2 * gq) * 68 + nc];
                split2(w0, w1, bh[nt][1], bl[nt][1]);
            }
#pragma unroll
            for (int mt = 0; mt < 2; mt++)
#pragma unroll
                for (int nt = 0; nt < 2; nt++) {
                    mma_bf16(acc[mt][nt], ah[mt], bh[nt]);
                    mma_bf16(acc[mt][nt], al[mt], bh[nt]);
                    mma_bf16(acc[mt][nt], ah[mt], bl[nt]);
                }
        }
        __syncthreads();
    }

#pragma unroll
    for (int mt = 0; mt < 2; mt++) {
#pragma unroll
        for (int nt = 0; nt < 2; nt++) {
            const float* ac = acc[mt][nt];
            const int row0 = mt * 16 + gr;
            const int col  = j0 + warp * 16 + nt * 8 + 2 * gq;
            if (ATOMIC) {
                if (col < N) {
                    atomicAdd(&C[(long)row0 * ldc + col], ac[0]);
                    atomicAdd(&C[(long)(row0 + 8) * ldc + col], ac[2]);
                }
                if (col + 1 < N) {
                    atomicAdd(&C[(long)row0 * ldc + col + 1], ac[1]);
                    atomicAdd(&C[(long)(row0 + 8) * ldc + col + 1], ac[3]);
                }
            } else {
                const float* bn = bias + (long)n * strideBias_n;
#pragma unroll
                for (int h = 0; h < 2; h++) {
                    const int j = col + h;
                    if (j < N) {
                        float v0 = ac[h]     + bn[j];
                        float v1 = ac[h + 2] + bn[j];
                        if (ORELU) { v0 = fmaxf(v0, 0.f); v1 = fmaxf(v1, 0.f); }
                        C[(long)row0 * ldc + j] = v0;
                        C[(long)(row0 + 8) * ldc + j] = v1;
                    }
                }
            }
        }
    }
}

// ---------------- launch ----------------
extern "C" void kernel_launch(void* const* d_in, const int* in_sizes, int n_in,
                              void* d_out, int out_size)
{
    const float* x   = (const float*)d_in[0];
    const float* cw1 = (const float*)d_in[1];
    const float* cb1 = (const float*)d_in[2];
    const float* cw2 = (const float*)d_in[3];
    const float* cb2 = (const float*)d_in[4];
    const float* cw3 = (const float*)d_in[5];
    const float* cb3 = (const float*)d_in[6];
    const float* wa  = (const float*)d_in[7];
    const float* ew1 = (const float*)d_in[9];
    const float* eb1 = (const float*)d_in[10];
    const float* ew2 = (const float*)d_in[11];
    const float* eb2 = (const float*)d_in[12];
    const float* ew3 = (const float*)d_in[13];
    const float* eb3 = (const float*)d_in[14];
    const float* fw1 = (const float*)d_in[15];
    const float* fb1 = (const float*)d_in[16];
    const float* fw2 = (const float*)d_in[17];
    const float* fb2 = (const float*)d_in[18];
    const float* fw3 = (const float*)d_in[19];
    const float* fb3 = (const float*)d_in[20];
    float* out = (float*)d_out;

    float *f, *lg, *att, *h1, *h2, *e, *g1, *g2;
    unsigned *p1h, *p1l, *p2h, *p2l, *wh2, *wl2, *wh3, *wl3;
    cudaGetSymbolAddress((void**)&p1h, g_p1h);
    cudaGetSymbolAddress((void**)&p1l, g_p1l);
    cudaGetSymbolAddress((void**)&p2h, g_p2h);
    cudaGetSymbolAddress((void**)&p2l, g_p2l);
    cudaGetSymbolAddress((void**)&f,   g_f);
    cudaGetSymbolAddress((void**)&lg,  g_lg);
    cudaGetSymbolAddress((void**)&att, g_at);
    cudaGetSymbolAddress((void**)&h1,  g_h1);
    cudaGetSymbolAddress((void**)&h2,  g_h2);
    cudaGetSymbolAddress((void**)&e,   g_e);
    cudaGetSymbolAddress((void**)&g1,  g_g1);
    cudaGetSymbolAddress((void**)&g2,  g_g2);
    cudaGetSymbolAddress((void**)&wh2, g_wh2);
    cudaGetSymbolAddress((void**)&wl2, g_wl2);
    cudaGetSymbolAddress((void**)&wh3, g_wh3);
    cudaGetSymbolAddress((void**)&wl3, g_wl3);

    conv_wprep_kernel<<<36, 256>>>(cw2, wh2, wl2, 32, 64);
    conv_wprep_kernel<<<144, 256>>>(cw3, wh3, wl3, 64, 128);

    // CNN stem (pair-plane dataflow, R13 layout)
    conv1_kernel<<<dim3(49, 4, 32), 256>>>(x, cw1, cb1, p1h, p1l);
    conv_bf_kernel<true, false><<<dim3(7, 14, 32), 256>>>(
        p1h, p1l, wh2, wl2, cb2, nullptr, p2h, p2l, nullptr, nullptr, 112, 112, 32, 64, 1);
    zero_kernel<<<16, 256>>>(lg, 32 * 128);
    conv_bf_kernel<false, true><<<dim3(4, 7, 64), 256>>>(
        p2h, p2l, wh3, wl3, cb3, f, nullptr, nullptr, wa, lg, 56, 56, 64, 128, 2);

    attn_softmax_kernel<<<32, 128>>>(lg, att);

    // experts
    gemm_bf_kernel<false, true, false, true><<<dim3(13, 128, 1), 128>>>(
        f, 784L, 128L * 784, att, ew1, 784L * 784, eb1, 784L, h1, 784L, 128L * 784, 784, 784);
    gemm_bf_kernel<false, false, false, true><<<dim3(7, 128, 1), 128>>>(
        h1, 784L, 128L * 784, nullptr, ew2, 784L * 392, eb2, 392L, h2, 392L, 128L * 392, 784, 392);
    gemm_bf_kernel<false, false, false, true><<<dim3(1, 128, 1), 128>>>(
        h2, 392L, 128L * 392, nullptr, ew3, 392L * 64, eb3, 64L, e, 64L, 8192L, 392, 64);

    // head: deeper k-splits to fill 148 SMs
    init_bias_kernel<<<1024, 256>>>(g1, fb1, FIN_, B_);
    gemm_bf_kernel<false, false, true, false><<<dim3(128, 1, 4), 128>>>(
        e, 0L, 8192L, nullptr, fw1, 0L, nullptr, 0L, g1, 0L, 8192L, 8192, 8192);

    init_bias_kernel<<<512, 256>>>(g2, fb2, FHID_, B_);
    gemm_bf_kernel<true, false, true, false><<<dim3(64, 1, 6), 128>>>(
        g1, 0L, 8192L, nullptr, fw2, 0L, nullptr, 0L, g2, 0L, 4096L, 8192, 4096);

    init_bias_kernel<<<7, 256>>>(out, fb3, OUT_, B_);
    gemm_bf_kernel<true, false, true, false><<<dim3(1, 1, 32), 128>>>(
        g2, 0L, 4096L, nullptr, fw3, 0L, nullptr, 0L, out, 0L, 53L, 4096, 53);
}